// round 6
// baseline (speedup 1.0000x reference)
#include <cuda_runtime.h>

// Nosé–Hoover chain (N_CHAIN=2) velocity-Verlet, B=1024, NDOF=64, 200 steps.
// Out: [traj_x (201,1024,64) | traj_v (201,1024,64)] fp32.
//
// R6: producer/consumer split in one grid.
//  - 8 chain blocks (warps 0-3 active, 1/SMSP): each lane runs ONE system's
//    full thermostat chain via the closed 3-moment recursion, publishing sv
//    per step into d_sv[step][sys] (coalesced STG.32), flag per 20-step chunk.
//  - 128 sweep blocks x 8 warps (1 system/warp, f32x2/lane): compute initial
//    moments (publish to chain via atomic counter), store snapshot 0, then
//    consume sv chunks (uniform __ldcg, 4-step prefetch) applying the linear
//    map x'=Ax+Bv, v'=Cx*x+Cv*v with B=dt*sv, Cx=cx0*sv, Cv=A*sv^2.
// The serial chain (~6us) and the L2-store-bound sweep (~9us) overlap:
// wall ~= store floor. Flags reset by a tiny init kernel (separate graph node).

namespace {
constexpr int NSYS   = 1024;
constexpr int NSTEP  = 200;
constexpr int CHUNK  = 20;
constexpr int NCHUNK = NSTEP / CHUNK;       // 10
constexpr int NGRP   = NSYS / 32;           // 32 chain groups
constexpr int F2SNAP = NSYS * 32;           // float2 per snapshot (32768)
}

__device__ float  d_sv[NSTEP][NSYS];        // per-step velocity scale factors
__device__ float4 d_mom[NSYS];              // initial (sxx, sxv, svv)
__device__ int    d_mcount[NGRP];           // moments-ready counters
__device__ int    d_cflag[NGRP];            // chunk-ready flags

#define FMA2(d,a,b,c) asm("fma.rn.f32x2 %0,%1,%2,%3;" : "=l"(d) : "l"(a), "l"(b), "l"(c))
#define MUL2(d,a,b)   asm("mul.rn.f32x2 %0,%1,%2;"    : "=l"(d) : "l"(a), "l"(b))
#define PACK2(d,f)    asm("mov.b64 %0,{%1,%1};"       : "=l"(d) : "f"(f))
#define PACKAB(d,a,b) asm("mov.b64 %0,{%1,%2};"       : "=l"(d) : "f"(a), "f"(b))
#define STG64(p,off,v) \
    asm volatile("st.global.b64 [%0+" #off "],%1;" :: "l"(p), "l"(v) : "memory")

// exp(-z) for |z| <= ~3e-4: 1 - z + z^2/2  (rel err ~ z^3/6 <= 5e-12)
__device__ __forceinline__ float expm(float z) {
    return fmaf(fmaf(0.5f, z, -1.0f), z, 1.0f);
}

// ---------------- chain producer (one system per lane) ----------------
__device__ __forceinline__ void chain_loop(float kT, float mass, float Q,
                                           float sxx, float sxv, float svv,
                                           int s, int g, int lane)
{
    const float dt   = 0.002f;
    const float dt4  = 0.25f  * dt;
    const float dt8  = 0.125f * dt;
    const float dth  = 0.5f   * dt;
    const float invQ = 1.0f / Q;
    const float c1   = dth / mass;
    const float A    = 1.0f - dt * c1;
    const float A2   = A * A;
    const float cx0  = -c1 * (1.0f + A);
    const float mIQ  = mass * invQ;
    const float nkIQ = -64.0f * kT * invQ;
    const float kTiQ = kT * invQ;
    const float m0c  = cx0 * cx0;
    const float m1c  = 2.0f * cx0 * A;
    const float p1c  = 2.0f * A * dt;
    const float p2c  = dt * dt;
    const float acx  = A * cx0;
    const float mc   = A2 + dt * cx0;
    const float dA   = dt * A;

    float xi0 = 0.0f, xi1 = 0.0f;
    float* psv = &d_sv[0][s];

    for (int c = 0; c < NCHUNK; ++c) {
        #pragma unroll 4
        for (int k = 0; k < CHUNK; ++k) {
            float G  = fmaf(mIQ, svv, nkIQ);
            xi1 = fmaf(dt4, G, xi1);
            float G0 = fmaf(xi0, xi0, -kTiQ);
            float z1 = xi1 * dt8;
            float se = expm(z1);
            float s2 = se * se;
            float dt4s = dt4 * se;
            float xi0a = fmaf(xi0, s2, G0 * dt4s);
            float z0 = xi0a * dth;
            float sv  = expm(z0);
            float sv2 = sv * sv;
            float m0 = m0c * sxx;
            float m1 = m1c * sxv;
            float m2 = A2  * svv;
            float svv_n = sv2 * fmaf(sv2, m2, fmaf(sv, m1, m0));
            float G2 = fmaf(mIQ, svv_n, nkIQ);
            xi0 = fmaf(dt4s, G2, xi0a * s2);
            float G3 = fmaf(xi0, xi0, -kTiQ);
            xi1 = fmaf(dt4, G3, xi1);
            float sxx_n = fmaf(p2c * sv2, svv, fmaf(p1c * sv, sxv, A2 * sxx));
            float sxv_n = fmaf((dA * sv) * sv2, svv,
                               fmaf(mc * sv2, sxv, (acx * sv) * sxx));
            sxx = sxx_n; sxv = sxv_n; svv = svv_n;
            *psv = sv;
            psv += NSYS;
        }
        __threadfence();
        if (lane == 0) atomicExch(&d_cflag[g], c + 1);
    }
}

// ---------------- fused kernel: roles by blockIdx ----------------
__global__ __launch_bounds__(256, 1)
void nhc_main(const float2* __restrict__ gx0,
              const float2* __restrict__ gv0,
              const float*  __restrict__ pkT,
              const float*  __restrict__ pmass,
              const float*  __restrict__ pQ,
              float2*       __restrict__ out)
{
    const int tid  = threadIdx.x;
    const int lane = tid & 31;
    const int wib  = tid >> 5;

    if (blockIdx.x < 8) {
        // ================= chain producer =================
        if (wib >= 4) return;                      // 1 chain warp per SMSP
        const int g = blockIdx.x * 4 + wib;        // group 0..31
        const int s = g * 32 + lane;               // this lane's system

        const float kT   = *pkT;
        const float mass = *pmass;
        const float Q    = *pQ;

        // wait for this group's 32 initial moments
        volatile int* mc = &d_mcount[g];
        while (*mc < 32) __nanosleep(64);
        __threadfence();
        const float4 m = __ldcg(&d_mom[s]);

        if (kT == 1.0f && mass == 1.0f && Q == 1.0f)
            chain_loop(1.0f, 1.0f, 1.0f, m.x, m.y, m.z, s, g, lane);
        else
            chain_loop(kT, mass, Q, m.x, m.y, m.z, s, g, lane);
        return;
    }

    // ================= sweep consumer =================
    const int s   = (blockIdx.x - 8) * 8 + wib;    // system id 0..1023
    const int g   = s >> 5;
    const int idx = s * 32 + lane;                 // float2 slot

    const float mass = *pmass;
    const float dt   = 0.002f;
    const float c1   = 0.5f * dt / mass;
    const float A    = 1.0f - dt * c1;
    const float cx0  = -c1 * (1.0f + A);

    const float2 x0 = gx0[idx];
    const float2 v0 = gv0[idx];

    // ---- initial moments -> publish to chain ----
    {
        float a = fmaf(x0.y, x0.y, x0.x * x0.x);
        float c = fmaf(x0.y, v0.y, x0.x * v0.x);
        float e = fmaf(v0.y, v0.y, v0.x * v0.x);
        #pragma unroll
        for (int msk = 1; msk <= 16; msk <<= 1) {
            a += __shfl_xor_sync(0xffffffffu, a, msk);
            c += __shfl_xor_sync(0xffffffffu, c, msk);
            e += __shfl_xor_sync(0xffffffffu, e, msk);
        }
        if (lane == 0) {
            d_mom[s] = make_float4(a, c, e, 0.0f);
            __threadfence();
            atomicAdd(&d_mcount[g], 1);
        }
    }

    // ---- snapshot 0 ----
    const float2* pxc = out + idx;                              // traj_x snap 0
    const float2* pvc = out + (size_t)(NSTEP + 1) * F2SNAP + idx;
    unsigned long long Xp, Vp, Ap, dtp, cx0p;
    PACKAB(Xp, x0.x, x0.y);
    PACKAB(Vp, v0.x, v0.y);
    PACK2(Ap, A); PACK2(dtp, dt); PACK2(cx0p, cx0);
    STG64(pxc, 0, Xp);
    STG64(pvc, 0, Vp);

    // ---- consume sv chunks ----
    volatile int* flag = &d_cflag[g];
    const float* psv = &d_sv[0][s];

    for (int c = 0; c < NCHUNK; ++c) {
        while (*flag < c + 1) __nanosleep(64);
        __threadfence();
        #pragma unroll 1
        for (int grp = 0; grp < CHUNK / 4; ++grp) {
            float svs[4];
            svs[0] = __ldcg(psv);
            svs[1] = __ldcg(psv + NSYS);
            svs[2] = __ldcg(psv + 2 * NSYS);
            svs[3] = __ldcg(psv + 3 * NSYS);
            psv += 4 * NSYS;
            #pragma unroll
            for (int j = 0; j < 4; ++j) {
                unsigned long long svp, sv2p, Bp, Cxp, Cvp, t, u, xn, vn;
                PACK2(svp, svs[j]);
                MUL2(sv2p, svp, svp);
                MUL2(Bp,  dtp,  svp);
                MUL2(Cxp, cx0p, svp);
                MUL2(Cvp, Ap,   sv2p);
                MUL2(t, Bp,  Vp);
                FMA2(xn, Ap,  Xp, t);
                MUL2(u, Cvp, Vp);
                FMA2(vn, Cxp, Xp, u);
                Xp = xn; Vp = vn;
                // store at snapshot (global_step + 1): offsets 1..4 snapshots
                if (j == 0) { STG64(pxc, 262144,  Xp); STG64(pvc, 262144,  Vp); }
                if (j == 1) { STG64(pxc, 524288,  Xp); STG64(pvc, 524288,  Vp); }
                if (j == 2) { STG64(pxc, 786432,  Xp); STG64(pvc, 786432,  Vp); }
                if (j == 3) { STG64(pxc, 1048576, Xp); STG64(pvc, 1048576, Vp); }
            }
            pxc += 4 * F2SNAP;
            pvc += 4 * F2SNAP;
        }
    }
}

__global__ void nhc_init()
{
    const int t = threadIdx.x;
    if (t < NGRP) {
        d_mcount[t] = 0;
        d_cflag[t]  = 0;
    }
}

extern "C" void kernel_launch(void* const* d_in, const int* in_sizes, int n_in,
                              void* d_out, int out_size)
{
    const float2* x0   = (const float2*)d_in[0];
    const float2* v0   = (const float2*)d_in[1];
    const float*  kT   = (const float*)d_in[2];
    const float*  mass = (const float*)d_in[3];
    const float*  Q    = (const float*)d_in[4];
    float2* out = (float2*)d_out;

    nhc_init<<<1, 64>>>();
    // 8 chain blocks + 128 sweep blocks = 136 <= 148 SMs: all resident, no deadlock
    nhc_main<<<136, 256>>>(x0, v0, kT, mass, Q, out);
}